// round 5
// baseline (speedup 1.0000x reference)
#include <cuda_runtime.h>
#include <math.h>
#include <stdint.h>

// ---------------------------------------------------------------------------
// Problem constants
// ---------------------------------------------------------------------------
#define NE 100000          // edges
#define NN 5000            // nodes
#define MUL 64
#define LATENT 256
#define NODE_DIM 64
#define RADIAL_DIM 8
#define W_ENV 128          // MUL*2
#define INV_SQRT3 0.5773502691896258f
#define INV_AVG 0.05f      // 1/20

// ---------------------------------------------------------------------------
// Scratch layout (single static device buffer; allocation-free)
// ---------------------------------------------------------------------------
#define SZ_CUT  ((size_t)NE)
#define SZ_X0   ((size_t)NE*136)
#define SZ_H0   ((size_t)NE*256)
#define SZ_H1   ((size_t)NE*256)
#define SZ_LAT  ((size_t)NE*256)
#define SZ_WALL ((size_t)NE*320)
#define SZ_FS   ((size_t)NE*64)
#define SZ_FV   ((size_t)NE*192)
#define SZ_FS2  ((size_t)NE*64)
#define SZ_FV2  ((size_t)NE*192)
#define SZ_TS   ((size_t)NE*128)
#define SZ_TV   ((size_t)NE*384)
#define SZ_FSO  ((size_t)NE*128)
#define SZ_FVO  ((size_t)NE*384)
#define SZ_FIN  ((size_t)NE*128)
#define SZ_NS   ((size_t)NN*64)
#define SZ_NV   ((size_t)NN*192)
#define SZ_WS   ((size_t)128*128)

#define OFF_CUT  ((size_t)0)
#define OFF_X0   (OFF_CUT + SZ_CUT)
#define OFF_H0   (OFF_X0 + SZ_X0)
#define OFF_H1   (OFF_H0 + SZ_H0)
#define OFF_LAT  (OFF_H1 + SZ_H1)
#define OFF_WALL (OFF_LAT + SZ_LAT)
#define OFF_FS   (OFF_WALL + SZ_WALL)
#define OFF_FV   (OFF_FS + SZ_FS)
#define OFF_FS2  (OFF_FV + SZ_FV)
#define OFF_FV2  (OFF_FS2 + SZ_FS2)
#define OFF_TS   (OFF_FV2 + SZ_FV2)
#define OFF_TV   (OFF_TS + SZ_TS)
#define OFF_FSO  (OFF_TV + SZ_TV)
#define OFF_FVO  (OFF_FSO + SZ_FSO)
#define OFF_FIN  (OFF_FVO + SZ_FVO)
#define OFF_NS   (OFF_FIN + SZ_FIN)     // NS and NV must stay contiguous (zeroed together)
#define OFF_NV   (OFF_NS + SZ_NS)
#define OFF_NS2  (OFF_NV + SZ_NV)
#define OFF_NV2  (OFF_NS2 + SZ_NS)
#define OFF_WS   (OFF_NV2 + SZ_NV)
#define OFF_WV   (OFF_WS + SZ_WS)
#define SCRATCH_TOTAL (OFF_WV + SZ_WS)

__device__ float g_scratch[SCRATCH_TOTAL];

// ---------------------------------------------------------------------------
// Generic fp32 GEMM: C[M,N] = epilogue( A[M,K] @ W[K,N] )
//   A may be a 2-way horizontal concat: cols [0,K1) from A1 (stride lda1),
//   cols [K1,K) from A2 (stride lda2). Requires K%8==0, N%64==0, K1%4==0.
//   act==1 -> SiLU; rowscale (optional) multiplies each output row.
// Tile: BM=128, BN=64, BK=8, 256 threads, 8x4 register tile.
// ---------------------------------------------------------------------------
__global__ __launch_bounds__(256) void gemm_kernel(
    const float* __restrict__ A1, int K1, int lda1,
    const float* __restrict__ A2, int lda2,
    const float* __restrict__ W,
    float* __restrict__ C,
    int M, int N, int K,
    int act, const float* __restrict__ rowscale)
{
    __shared__ __align__(16) float As[8][128];
    __shared__ __align__(16) float Bs[8][64];

    const int tid = threadIdx.x;
    const int tx  = tid & 15;      // 0..15 -> output col group (4 cols)
    const int ty  = tid >> 4;      // 0..15 -> output row group (8 rows)
    const int bm  = blockIdx.y * 128;
    const int bn  = blockIdx.x * 64;

    const int arow  = tid >> 1;          // 0..127
    const int akoff = (tid & 1) << 2;    // 0 or 4
    const int brow  = tid >> 4;          // 0..15 (only <8 used when tid<128)
    const int bcol  = (tid & 15) << 2;   // 0..60

    float acc[8][4];
    #pragma unroll
    for (int i = 0; i < 8; i++)
        #pragma unroll
        for (int j = 0; j < 4; j++) acc[i][j] = 0.f;

    const int grow = bm + arow;

    for (int k0 = 0; k0 < K; k0 += 8) {
        float4 av = make_float4(0.f, 0.f, 0.f, 0.f);
        if (grow < M) {
            int k = k0 + akoff;
            if (k < K1) av = *reinterpret_cast<const float4*>(A1 + (size_t)grow * lda1 + k);
            else        av = *reinterpret_cast<const float4*>(A2 + (size_t)grow * lda2 + (k - K1));
        }
        float4 bv = make_float4(0.f, 0.f, 0.f, 0.f);
        if (tid < 128) {
            int k = k0 + brow;
            bv = *reinterpret_cast<const float4*>(W + (size_t)k * N + bn + bcol);
        }
        __syncthreads();
        As[akoff + 0][arow] = av.x;
        As[akoff + 1][arow] = av.y;
        As[akoff + 2][arow] = av.z;
        As[akoff + 3][arow] = av.w;
        if (tid < 128)
            *reinterpret_cast<float4*>(&Bs[brow][bcol]) = bv;
        __syncthreads();

        #pragma unroll
        for (int kk = 0; kk < 8; kk++) {
            float4 a0 = *reinterpret_cast<const float4*>(&As[kk][ty * 8]);
            float4 a1 = *reinterpret_cast<const float4*>(&As[kk][ty * 8 + 4]);
            float4 b  = *reinterpret_cast<const float4*>(&Bs[kk][tx * 4]);
            float a[8] = {a0.x, a0.y, a0.z, a0.w, a1.x, a1.y, a1.z, a1.w};
            float bb[4] = {b.x, b.y, b.z, b.w};
            #pragma unroll
            for (int i = 0; i < 8; i++)
                #pragma unroll
                for (int j = 0; j < 4; j++)
                    acc[i][j] = fmaf(a[i], bb[j], acc[i][j]);
        }
    }

    #pragma unroll
    for (int i = 0; i < 8; i++) {
        int r = bm + ty * 8 + i;
        if (r >= M) continue;
        float sc = rowscale ? rowscale[r] : 1.f;
        float4 o;
        float* po = &o.x;
        #pragma unroll
        for (int j = 0; j < 4; j++) {
            float v = acc[i][j];
            if (act) v = v * (1.f / (1.f + __expf(-v)));   // SiLU
            po[j] = v * sc;
        }
        *reinterpret_cast<float4*>(C + (size_t)r * N + bn + tx * 4) = o;
    }
}

// ---------------------------------------------------------------------------
// Elementwise kernels
// ---------------------------------------------------------------------------
__global__ void k_zero(float* __restrict__ p, int n) {
    int t = blockIdx.x * blockDim.x + threadIdx.x;
    if (t < n) p[t] = 0.f;
}

__global__ void k_cut(const float* __restrict__ len, float* __restrict__ cut) {
    int e = blockIdx.x * blockDim.x + threadIdx.x;
    if (e >= NE) return;
    float x = len[e] * 0.2f;                 // r / R_MAX, R_MAX=5
    float x2 = x * x;
    float x6 = x2 * x2 * x2;
    float out = 1.f - 28.f * x6 + 48.f * x6 * x - 21.f * x6 * x2;   // p=6
    cut[e] = (x < 1.f) ? out : 0.f;
}

// X0[e] = concat(node[center] (64), node[neigh] (64), radial (8))
__global__ void k_gather(const float* __restrict__ nodes,
                         const float* __restrict__ radial,
                         const int* __restrict__ eidx,
                         float* __restrict__ X0)
{
    int t = blockIdx.x * blockDim.x + threadIdx.x;
    if (t >= NE * 136) return;
    int e = t / 136;
    int j = t - e * 136;
    float v;
    if (j < 64)       v = nodes[(size_t)eidx[e] * 64 + j];
    else if (j < 128) v = nodes[(size_t)eidx[NE + e] * 64 + (j - 64)];
    else              v = radial[(size_t)e * 8 + (j - 128)];
    X0[t] = v;
}

// Stage-1 env: wall (E,320) -> fs (E,64), fv (E,3,64); scatter es/ev into NS/NV.
__global__ void k_env0(const float* __restrict__ wall,
                       const float* __restrict__ ang,
                       const int* __restrict__ center,
                       float* __restrict__ fs, float* __restrict__ fv,
                       float* __restrict__ ns, float* __restrict__ nv)
{
    int t = blockIdx.x * blockDim.x + threadIdx.x;
    if (t >= NE * 64) return;
    int e = t >> 6, u = t & 63;
    const float* w = wall + (size_t)e * 320;
    float g   = w[128 + u];
    float we0 = w[2 * u],       we1 = w[2 * u + 1];
    float wf0 = w[192 + 2 * u], wf1 = w[192 + 2 * u + 1];
    float s0 = ang[e * 4], s1 = ang[e * 4 + 1], s2 = ang[e * 4 + 2], s3 = ang[e * 4 + 3];
    fs[t] = wf0 * s0 * g;
    size_t fb = (size_t)e * 192 + u;
    fv[fb]        = wf1 * s1 * g;
    fv[fb + 64]   = wf1 * s2 * g;
    fv[fb + 128]  = wf1 * s3 * g;
    int ce = center[e];
    atomicAdd(&ns[(size_t)ce * 64 + u], we0 * s0);
    size_t nb = (size_t)ce * 192 + u;
    atomicAdd(&nv[nb],        we1 * s1);
    atomicAdd(&nv[nb + 64],   we1 * s2);
    atomicAdd(&nv[nb + 128],  we1 * s3);
}

// Stage-2 env: wall (E,192); gate existing fs/fv in place; scatter es/ev.
__global__ void k_env1(const float* __restrict__ wall,
                       const float* __restrict__ ang,
                       const int* __restrict__ center,
                       float* __restrict__ fs, float* __restrict__ fv,
                       float* __restrict__ ns, float* __restrict__ nv)
{
    int t = blockIdx.x * blockDim.x + threadIdx.x;
    if (t >= NE * 64) return;
    int e = t >> 6, u = t & 63;
    const float* w = wall + (size_t)e * 192;
    float g   = w[128 + u];
    float we0 = w[2 * u], we1 = w[2 * u + 1];
    float s0 = ang[e * 4], s1 = ang[e * 4 + 1], s2 = ang[e * 4 + 2], s3 = ang[e * 4 + 3];
    fs[t] *= g;
    size_t fb = (size_t)e * 192 + u;
    fv[fb]       *= g;
    fv[fb + 64]  *= g;
    fv[fb + 128] *= g;
    int ce = center[e];
    atomicAdd(&ns[(size_t)ce * 64 + u], we0 * s0);
    size_t nb = (size_t)ce * 192 + u;
    atomicAdd(&nv[nb],       we1 * s1);
    atomicAdd(&nv[nb + 64],  we1 * s2);
    atomicAdd(&nv[nb + 128], we1 * s3);
}

// Per-node 64x64 linear on s-channel (w0) and each vector comp (w1). /AVG_NEIGH folded.
__global__ void k_nodelin(const float* __restrict__ ns, const float* __restrict__ nv,
                          const float* __restrict__ w0, const float* __restrict__ w1,
                          float* __restrict__ ns2, float* __restrict__ nv2)
{
    __shared__ float sm[256];      // [0:64) s, [64:256) v (c-major)
    int n = blockIdx.x;
    int tid = threadIdx.x;
    if (tid < 64)       sm[tid] = ns[(size_t)n * 64 + tid] * INV_AVG;
    else                sm[tid] = nv[(size_t)n * 192 + (tid - 64)] * INV_AVG;
    __syncthreads();
    int v = tid & 63;
    int grp = tid >> 6;            // 0 = scalar, 1..3 = vector comps
    const float* w  = (grp == 0) ? w0 : w1;
    const float* in = (grp == 0) ? &sm[0] : &sm[grp * 64];  // grp*64 = 64 + (grp-1)*64
    float acc = 0.f;
    #pragma unroll 8
    for (int u = 0; u < 64; u++)
        acc = fmaf(in[u], w[u * 64 + v], acc);
    if (grp == 0) ns2[(size_t)n * 64 + v] = acc;
    else          nv2[(size_t)n * 192 + (grp - 1) * 64 + v] = acc;
}

// Tensor product uuu: fs/fv (edge) x ns2/nv2[center] -> TS (E,128), TV (3E,128)
__global__ void k_tp(const float* __restrict__ fs, const float* __restrict__ fv,
                     const float* __restrict__ ns2, const float* __restrict__ nv2,
                     const int* __restrict__ center,
                     float* __restrict__ ts, float* __restrict__ tv)
{
    int t = blockIdx.x * blockDim.x + threadIdx.x;
    if (t >= NE * 64) return;
    int e = t >> 6, u = t & 63;
    int ce = center[e];
    float s1  = fs[t];
    size_t fb = (size_t)e * 192 + u;
    float v1x = fv[fb], v1y = fv[fb + 64], v1z = fv[fb + 128];
    float s2  = ns2[(size_t)ce * 64 + u];
    size_t nb = (size_t)ce * 192 + u;
    float v2x = nv2[nb], v2y = nv2[nb + 64], v2z = nv2[nb + 128];

    ts[(size_t)e * 128 + u]      = s1 * s2;
    ts[(size_t)e * 128 + 64 + u] = (v1x * v2x + v1y * v2y + v1z * v2z) * INV_SQRT3;

    size_t tb = (size_t)e * 384;   // rows (e*3+c) of width 128 -> e*384 + c*128
    tv[tb + u]             = s1 * v2x * INV_SQRT3;
    tv[tb + 64 + u]        = v1x * s2 * INV_SQRT3;
    tv[tb + 128 + u]       = s1 * v2y * INV_SQRT3;
    tv[tb + 128 + 64 + u]  = v1y * s2 * INV_SQRT3;
    tv[tb + 256 + u]       = s1 * v2z * INV_SQRT3;
    tv[tb + 256 + 64 + u]  = v1z * s2 * INV_SQRT3;
}

// Residual update: lat = sqrt(1-a)*lat + sqrt(a)*cut*new_lat, a = sigmoid(res_p[1])
__global__ void k_resid(float* __restrict__ lat, const float* __restrict__ nl,
                        const float* __restrict__ cut, const float* __restrict__ res_p)
{
    int t = blockIdx.x * blockDim.x + threadIdx.x;
    if (t >= NE * 256) return;
    float a = 1.f / (1.f + expf(-res_p[1]));
    float sa = sqrtf(1.f - a), sb = sqrtf(a);
    int e = t >> 8;
    lat[t] = sa * lat[t] + sb * cut[e] * nl[t];
}

// lin1_{sw,vw} (i,o,u,v) -> W[(i*64+u), (o*64+v)] (128x128)
__global__ void k_transpose(const float* __restrict__ sw, const float* __restrict__ vw,
                            float* __restrict__ WS, float* __restrict__ WV)
{
    int t = blockIdx.x * blockDim.x + threadIdx.x;
    if (t >= 2 * 2 * 64 * 64) return;
    int v = t & 63;
    int u = (t >> 6) & 63;
    int o = (t >> 12) & 1;
    int i = (t >> 13) & 1;
    int dst = (i * 64 + u) * 128 + (o * 64 + v);
    WS[dst] = sw[t];
    WV[dst] = vw[t];
}

// Output assembly: out (E,512) = [fs*fin (128) | fv (2*64*3 = 384)]
__global__ void k_out(const float* __restrict__ fso, const float* __restrict__ fvo,
                      const float* __restrict__ fin, float* __restrict__ out)
{
    int t = blockIdx.x * blockDim.x + threadIdx.x;
    if (t >= NE * 512) return;
    int e = t >> 9;
    int j = t & 511;
    if (j < 128) {
        out[t] = fso[(size_t)e * 128 + j] * fin[(size_t)e * 128 + j];
    } else {
        int r = j - 128;
        int o = r / 192;
        int q = r - o * 192;
        int v = q / 3;
        int c = q - v * 3;
        out[t] = fvo[((size_t)e * 3 + c) * 128 + o * 64 + v];
    }
}

// ---------------------------------------------------------------------------
// Host orchestration
// ---------------------------------------------------------------------------
static inline int cdiv(int a, int b) { return (a + b - 1) / b; }

static void run_gemm(const float* A1, int K1, int lda1,
                     const float* A2, int lda2,
                     const float* W, float* C,
                     int M, int N, int K, int act, const float* rs)
{
    dim3 grid(N / 64, cdiv(M, 128));
    gemm_kernel<<<grid, 256>>>(A1, K1, lda1, A2, lda2, W, C, M, N, K, act, rs);
}

extern "C" void kernel_launch(void* const* d_in, const int* in_sizes, int n_in,
                              void* d_out, int out_size)
{
    const float* node_attrs = (const float*)d_in[0];
    const float* radial     = (const float*)d_in[1];
    const float* ang        = (const float*)d_in[2];
    const float* lens       = (const float*)d_in[3];
    const int*   eidx       = (const int*)d_in[4];
    const float* tb_w0      = (const float*)d_in[5];
    const float* tb_w1      = (const float*)d_in[6];
    const float* tb_w2      = (const float*)d_in[7];
    const float* lat1_w0    = (const float*)d_in[8];
    const float* lat1_w1    = (const float*)d_in[9];
    const float* env0_w     = (const float*)d_in[10];
    const float* env1_w     = (const float*)d_in[11];
    const float* envlin0    = (const float*)d_in[12];
    const float* envlin1    = (const float*)d_in[13];
    const float* lin0_sw    = (const float*)d_in[14];
    const float* lin0_vw    = (const float*)d_in[15];
    const float* lin1_sw    = (const float*)d_in[16];
    const float* lin1_vw    = (const float*)d_in[17];
    const float* fin_w0     = (const float*)d_in[18];
    const float* fin_w1     = (const float*)d_in[19];
    const float* res_p      = (const float*)d_in[20];
    float* out = (float*)d_out;

    float* S = nullptr;
    cudaGetSymbolAddress((void**)&S, g_scratch);

    float* CUT  = S + OFF_CUT;
    float* X0   = S + OFF_X0;
    float* H0   = S + OFF_H0;
    float* H1   = S + OFF_H1;
    float* LAT  = S + OFF_LAT;
    float* WALL = S + OFF_WALL;
    float* FS   = S + OFF_FS;
    float* FV   = S + OFF_FV;
    float* FS2  = S + OFF_FS2;
    float* FV2  = S + OFF_FV2;
    float* TS   = S + OFF_TS;
    float* TV   = S + OFF_TV;
    float* FSO  = S + OFF_FSO;
    float* FVO  = S + OFF_FVO;
    float* FIN  = S + OFF_FIN;
    float* NS   = S + OFF_NS;
    float* NV   = S + OFF_NV;
    float* NS2  = S + OFF_NS2;
    float* NV2  = S + OFF_NV2;
    float* WS   = S + OFF_WS;
    float* WV   = S + OFF_WV;

    const int T = 256;

    // cutoff + gather/concat
    k_cut<<<cdiv(NE, T), T>>>(lens, CUT);
    k_gather<<<cdiv(NE * 136, T), T>>>(node_attrs, radial, eidx, X0);

    // two-body MLP -> latents (cut applied in epilogue)
    run_gemm(X0, 136, 136, nullptr, 0, tb_w0, H0, NE, 256, 136, 1, nullptr);
    run_gemm(H0, 256, 256, nullptr, 0, tb_w1, H1, NE, 256, 256, 1, nullptr);
    run_gemm(H1, 256, 256, nullptr, 0, tb_w2, LAT, NE, 256, 256, 0, CUT);

    // env0 weights
    run_gemm(LAT, 256, 256, nullptr, 0, env0_w, WALL, NE, 320, 256, 0, nullptr);

    // env weighting + scatter (NS,NV contiguous -> one zero pass)
    k_zero<<<cdiv(NN * 256, T), T>>>(NS, NN * 256);
    k_env0<<<cdiv(NE * 64, T), T>>>(WALL, ang, eidx, FS, FV, NS, NV);
    k_nodelin<<<NN, 256>>>(NS, NV, envlin0, envlin0 + 4096, NS2, NV2);

    // tensor product 1 -> TS (E,128), TV (3E,128)
    k_tp<<<cdiv(NE * 64, T), T>>>(FS, FV, NS2, NV2, eidx, TS, TV);

    // lin0 (einsums as GEMMs)
    run_gemm(TS, 128, 128, nullptr, 0, lin0_sw, FS2, NE, 64, 128, 0, nullptr);
    run_gemm(TV, 128, 128, nullptr, 0, lin0_vw, FV2, 3 * NE, 64, 128, 0, nullptr);

    // latent MLP on concat(LAT, TS) -> new latents (H1), residual mix
    run_gemm(LAT, 256, 256, TS, 128, lat1_w0, H0, NE, 256, 384, 1, nullptr);
    run_gemm(H0, 256, 256, nullptr, 0, lat1_w1, H1, NE, 256, 256, 0, nullptr);
    k_resid<<<cdiv(NE * 256, T), T>>>(LAT, H1, CUT, res_p);

    // env1
    run_gemm(LAT, 256, 256, nullptr, 0, env1_w, WALL, NE, 192, 256, 0, nullptr);
    k_zero<<<cdiv(NN * 256, T), T>>>(NS, NN * 256);
    k_env1<<<cdiv(NE * 64, T), T>>>(WALL, ang, eidx, FS2, FV2, NS, NV);
    k_nodelin<<<NN, 256>>>(NS, NV, envlin1, envlin1 + 4096, NS2, NV2);

    // tensor product 2 -> TS/TV (reuse)
    k_tp<<<cdiv(NE * 64, T), T>>>(FS2, FV2, NS2, NV2, eidx, TS, TV);

    // lin1 (transpose weights into GEMM layout, then GEMMs)
    k_transpose<<<cdiv(16384, T), T>>>(lin1_sw, lin1_vw, WS, WV);
    run_gemm(TS, 128, 128, nullptr, 0, WS, FSO, NE, 128, 128, 0, nullptr);
    run_gemm(TV, 128, 128, nullptr, 0, WV, FVO, 3 * NE, 128, 128, 0, nullptr);

    // final MLP on concat(LAT, TS)
    run_gemm(LAT, 256, 256, TS, 128, fin_w0, H0, NE, 256, 384, 1, nullptr);
    run_gemm(H0, 256, 256, nullptr, 0, fin_w1, FIN, NE, 128, 256, 0, nullptr);

    // output assembly
    k_out<<<cdiv(NE * 512, T), T>>>(FSO, FVO, FIN, out);
}

// round 10
// speedup vs baseline: 1.6206x; 1.6206x over previous
#include <cuda_runtime.h>
#include <cuda_bf16.h>
#include <math.h>
#include <stdint.h>

// ---------------------------------------------------------------------------
// Problem constants
// ---------------------------------------------------------------------------
#define NE 100000
#define NN 5000
#define INV_SQRT3 0.5773502691896258f
#define INV_AVG 0.05f

// ---------------------------------------------------------------------------
// Scratch layout
// ---------------------------------------------------------------------------
#define SZ_CUT  ((size_t)NE)
#define SZ_X0   ((size_t)NE*136)
#define SZ_H0   ((size_t)NE*256)
#define SZ_H1   ((size_t)NE*256)
#define SZ_LAT  ((size_t)NE*256)
#define SZ_WALL ((size_t)NE*320)
#define SZ_FS   ((size_t)NE*64)
#define SZ_FV   ((size_t)NE*192)
#define SZ_TS   ((size_t)NE*128)
#define SZ_TV   ((size_t)NE*384)
#define SZ_NS   ((size_t)NN*64)
#define SZ_NV   ((size_t)NN*192)
#define SZ_WS   ((size_t)128*128)

#define OFF_CUT  ((size_t)0)
#define OFF_X0   (OFF_CUT + SZ_CUT)
#define OFF_H0   (OFF_X0 + SZ_X0)
#define OFF_H1   (OFF_H0 + SZ_H0)
#define OFF_LAT  (OFF_H1 + SZ_H1)
#define OFF_WALL (OFF_LAT + SZ_LAT)
#define OFF_FS   (OFF_WALL + SZ_WALL)
#define OFF_FV   (OFF_FS + SZ_FS)
#define OFF_FS2  (OFF_FV + SZ_FV)
#define OFF_FV2  (OFF_FS2 + SZ_FS)
#define OFF_TS   (OFF_FV2 + SZ_FV)
#define OFF_TV   (OFF_TS + SZ_TS)
#define OFF_FSO  (OFF_TV + SZ_TV)
#define OFF_FVO  (OFF_FSO + SZ_TS)
#define OFF_FIN2 (OFF_FVO + SZ_TV)
#define OFF_NS   (OFF_FIN2 + SZ_TS)
#define OFF_NV   (OFF_NS + SZ_NS)
#define OFF_NS2  (OFF_NV + SZ_NV)
#define OFF_NV2  (OFF_NS2 + SZ_NS)
#define OFF_WSC  (OFF_NV2 + SZ_NV)
#define OFF_WVC  (OFF_WSC + SZ_WS)
#define SCRATCH_TOTAL (OFF_WVC + SZ_WS)

__device__ float g_scratch[SCRATCH_TOTAL];

// ---------------------------------------------------------------------------
// HMMA helpers (plain sm_80+ PTX — legal on the compute_103 target)
// ---------------------------------------------------------------------------
__device__ __forceinline__ void mma16816(float* c, const uint32_t* a, const uint32_t* b) {
    asm volatile(
        "mma.sync.aligned.m16n8k16.row.col.f32.bf16.bf16.f32 "
        "{%0,%1,%2,%3}, {%4,%5,%6,%7}, {%8,%9}, {%0,%1,%2,%3};"
        : "+f"(c[0]), "+f"(c[1]), "+f"(c[2]), "+f"(c[3])
        : "r"(a[0]), "r"(a[1]), "r"(a[2]), "r"(a[3]), "r"(b[0]), "r"(b[1]));
}

__device__ __forceinline__ uint32_t pack_bf16(float lo, float hi) {
    __nv_bfloat162 t = __floats2bfloat162_rn(lo, hi);
    return *reinterpret_cast<uint32_t*>(&t);
}

// ---------------------------------------------------------------------------
// Tensor-core GEMM: C[M,N] = epi( A[M,K] @ W[K,N] )
//   split-bf16 (hi/lo) x 3 HMMA passes, fp32 accumulate.
//   A optionally 2-way concat (A1 cols [0,K1), A2 cols [K1,K)); K1 % 4 == 0.
//   N % 64 == 0; K % 4 == 0 (K tail beyond chunk zero-padded); M tail guarded.
// Tile: BM=128, BN=64, K-chunk=32; 256 threads (8 warps, each 32x32 of C).
// SMEM rows padded to 40 bf16 (80B) -> fragment LDS pattern 20g+t is
// conflict-free across a warp.
// ---------------------------------------------------------------------------
#define LDK 40   // padded row length in bf16

__global__ __launch_bounds__(256)
void gemm_tc(const float* __restrict__ A1, int K1, int lda1,
             const float* __restrict__ A2, int lda2,
             const float* __restrict__ W,
             float* __restrict__ C,
             int M, int N, int K,
             int act, const float* __restrict__ rowscale)
{
    __shared__ __align__(16) char sAh[128 * LDK * 2];
    __shared__ __align__(16) char sAl[128 * LDK * 2];
    __shared__ __align__(16) char sBh[64 * LDK * 2];
    __shared__ __align__(16) char sBl[64 * LDK * 2];

    const int tid = threadIdx.x;
    const int wid = tid >> 5;
    const int lid = tid & 31;
    const int g = lid >> 2;       // group id 0..7
    const int t = lid & 3;        // thread-in-group
    const int wm = (wid >> 1) * 32;
    const int wn = (wid & 1) * 32;
    const int bm = blockIdx.y * 128;
    const int bn = blockIdx.x * 64;

    float acc[2][4][4];
    #pragma unroll
    for (int i = 0; i < 2; i++)
        #pragma unroll
        for (int j = 0; j < 4; j++)
            #pragma unroll
            for (int q = 0; q < 4; q++) acc[i][j][q] = 0.f;

    const int nch = (K + 31) / 32;

    // prefetch registers
    float4 aP[4];
    float  bP[8];

    // ---- tile loaders ----
    auto load_tile = [&](int c) {
        const int k0 = c * 32;
        #pragma unroll
        for (int it = 0; it < 4; it++) {
            int f = tid + it * 256;          // 1024 float4 = 128 rows x 8
            int row = f >> 3, kc = (f & 7) << 2;
            int gr = bm + row, gk = k0 + kc;
            float4 v = make_float4(0.f, 0.f, 0.f, 0.f);
            if (gr < M && gk < K) {
                v = (gk < K1)
                    ? *reinterpret_cast<const float4*>(A1 + (size_t)gr * lda1 + gk)
                    : *reinterpret_cast<const float4*>(A2 + (size_t)gr * lda2 + (gk - K1));
            }
            aP[it] = v;
        }
        #pragma unroll
        for (int it = 0; it < 2; it++) {
            int f = tid + it * 256;          // 512 slots = 64 n x 8 k-groups
            int n = f & 63, kb = (f >> 6) << 2;
            #pragma unroll
            for (int i = 0; i < 4; i++) {
                int gk = k0 + kb + i;
                bP[it * 4 + i] = (gk < K) ? W[(size_t)gk * N + bn + n] : 0.f;
            }
        }
    };

    auto store_tile = [&]() {
        #pragma unroll
        for (int it = 0; it < 4; it++) {
            int f = tid + it * 256;
            int row = f >> 3, kc = (f & 7) << 2;
            float4 v = aP[it];
            float h0 = __bfloat162float(__float2bfloat16_rn(v.x));
            float h1 = __bfloat162float(__float2bfloat16_rn(v.y));
            float h2 = __bfloat162float(__float2bfloat16_rn(v.z));
            float h3 = __bfloat162float(__float2bfloat16_rn(v.w));
            uint32_t off = row * (LDK * 2) + kc * 2;
            *reinterpret_cast<uint2*>(sAh + off) =
                make_uint2(pack_bf16(h0, h1), pack_bf16(h2, h3));
            *reinterpret_cast<uint2*>(sAl + off) =
                make_uint2(pack_bf16(v.x - h0, v.y - h1), pack_bf16(v.z - h2, v.w - h3));
        }
        #pragma unroll
        for (int it = 0; it < 2; it++) {
            int f = tid + it * 256;
            int n = f & 63, kb = (f >> 6) << 2;
            float v0 = bP[it * 4 + 0], v1 = bP[it * 4 + 1];
            float v2 = bP[it * 4 + 2], v3 = bP[it * 4 + 3];
            float h0 = __bfloat162float(__float2bfloat16_rn(v0));
            float h1 = __bfloat162float(__float2bfloat16_rn(v1));
            float h2 = __bfloat162float(__float2bfloat16_rn(v2));
            float h3 = __bfloat162float(__float2bfloat16_rn(v3));
            uint32_t off = n * (LDK * 2) + kb * 2;
            *reinterpret_cast<uint2*>(sBh + off) =
                make_uint2(pack_bf16(h0, h1), pack_bf16(h2, h3));
            *reinterpret_cast<uint2*>(sBl + off) =
                make_uint2(pack_bf16(v0 - h0, v1 - h1), pack_bf16(v2 - h2, v3 - h3));
        }
    };

    load_tile(0);
    store_tile();
    __syncthreads();

    for (int c = 0; c < nch; c++) {
        if (c + 1 < nch) load_tile(c + 1);

        // ---- compute from smem ----
        #pragma unroll
        for (int kk = 0; kk < 2; kk++) {
            uint32_t ah[2][4], al[2][4], bh[4][2], bl[4][2];
            #pragma unroll
            for (int mt = 0; mt < 2; mt++) {
                uint32_t base = (wm + mt * 16 + g) * (LDK * 2) + kk * 32 + t * 4;
                ah[mt][0] = *reinterpret_cast<const uint32_t*>(sAh + base);
                ah[mt][1] = *reinterpret_cast<const uint32_t*>(sAh + base + 8 * (LDK * 2));
                ah[mt][2] = *reinterpret_cast<const uint32_t*>(sAh + base + 16);
                ah[mt][3] = *reinterpret_cast<const uint32_t*>(sAh + base + 8 * (LDK * 2) + 16);
                al[mt][0] = *reinterpret_cast<const uint32_t*>(sAl + base);
                al[mt][1] = *reinterpret_cast<const uint32_t*>(sAl + base + 8 * (LDK * 2));
                al[mt][2] = *reinterpret_cast<const uint32_t*>(sAl + base + 16);
                al[mt][3] = *reinterpret_cast<const uint32_t*>(sAl + base + 8 * (LDK * 2) + 16);
            }
            #pragma unroll
            for (int nt = 0; nt < 4; nt++) {
                uint32_t base = (wn + nt * 8 + g) * (LDK * 2) + kk * 32 + t * 4;
                bh[nt][0] = *reinterpret_cast<const uint32_t*>(sBh + base);
                bh[nt][1] = *reinterpret_cast<const uint32_t*>(sBh + base + 16);
                bl[nt][0] = *reinterpret_cast<const uint32_t*>(sBl + base);
                bl[nt][1] = *reinterpret_cast<const uint32_t*>(sBl + base + 16);
            }
            #pragma unroll
            for (int mt = 0; mt < 2; mt++)
                #pragma unroll
                for (int nt = 0; nt < 4; nt++) {
                    mma16816(acc[mt][nt], ah[mt], bh[nt]);
                    mma16816(acc[mt][nt], ah[mt], bl[nt]);
                    mma16816(acc[mt][nt], al[mt], bh[nt]);
                }
        }
        __syncthreads();
        if (c + 1 < nch) {
            store_tile();
            __syncthreads();
        }
    }

    // ---- epilogue ----
    #pragma unroll
    for (int mt = 0; mt < 2; mt++) {
        #pragma unroll
        for (int half = 0; half < 2; half++) {
            int r = bm + wm + mt * 16 + g + half * 8;
            if (r >= M) continue;
            float sc = rowscale ? rowscale[r] : 1.f;
            #pragma unroll
            for (int nt = 0; nt < 4; nt++) {
                float v0 = acc[mt][nt][half * 2 + 0];
                float v1 = acc[mt][nt][half * 2 + 1];
                if (act) {
                    v0 = v0 * (1.f / (1.f + __expf(-v0)));
                    v1 = v1 * (1.f / (1.f + __expf(-v1)));
                }
                float2 o = make_float2(v0 * sc, v1 * sc);
                *reinterpret_cast<float2*>(C + (size_t)r * N + bn + wn + nt * 8 + 2 * t) = o;
            }
        }
    }
}

// ---------------------------------------------------------------------------
// Elementwise kernels
// ---------------------------------------------------------------------------
__global__ void k_zero(float* __restrict__ p, int n) {
    int t = blockIdx.x * blockDim.x + threadIdx.x;
    if (t < n) p[t] = 0.f;
}

__global__ void k_cut(const float* __restrict__ len, float* __restrict__ cut) {
    int e = blockIdx.x * blockDim.x + threadIdx.x;
    if (e >= NE) return;
    float x = len[e] * 0.2f;
    float x2 = x * x;
    float x6 = x2 * x2 * x2;
    float out = 1.f - 28.f * x6 + 48.f * x6 * x - 21.f * x6 * x2;
    cut[e] = (x < 1.f) ? out : 0.f;
}

__global__ void k_gather(const float* __restrict__ nodes,
                         const float* __restrict__ radial,
                         const int* __restrict__ eidx,
                         float* __restrict__ X0)
{
    int t = blockIdx.x * blockDim.x + threadIdx.x;
    if (t >= NE * 136) return;
    int e = t / 136;
    int j = t - e * 136;
    float v;
    if (j < 64)       v = nodes[(size_t)eidx[e] * 64 + j];
    else if (j < 128) v = nodes[(size_t)eidx[NE + e] * 64 + (j - 64)];
    else              v = radial[(size_t)e * 8 + (j - 128)];
    X0[t] = v;
}

__global__ void k_env0(const float* __restrict__ wall,
                       const float* __restrict__ ang,
                       const int* __restrict__ center,
                       float* __restrict__ fs, float* __restrict__ fv,
                       float* __restrict__ ns, float* __restrict__ nv)
{
    int t = blockIdx.x * blockDim.x + threadIdx.x;
    if (t >= NE * 64) return;
    int e = t >> 6, u = t & 63;
    const float* w = wall + (size_t)e * 320;
    float g   = w[128 + u];
    float we0 = w[2 * u],       we1 = w[2 * u + 1];
    float wf0 = w[192 + 2 * u], wf1 = w[192 + 2 * u + 1];
    float s0 = ang[e * 4], s1 = ang[e * 4 + 1], s2 = ang[e * 4 + 2], s3 = ang[e * 4 + 3];
    fs[t] = wf0 * s0 * g;
    size_t fb = (size_t)e * 192 + u;
    fv[fb]        = wf1 * s1 * g;
    fv[fb + 64]   = wf1 * s2 * g;
    fv[fb + 128]  = wf1 * s3 * g;
    int ce = center[e];
    atomicAdd(&ns[(size_t)ce * 64 + u], we0 * s0);
    size_t nb = (size_t)ce * 192 + u;
    atomicAdd(&nv[nb],        we1 * s1);
    atomicAdd(&nv[nb + 64],   we1 * s2);
    atomicAdd(&nv[nb + 128],  we1 * s3);
}

__global__ void k_env1(const float* __restrict__ wall,
                       const float* __restrict__ ang,
                       const int* __restrict__ center,
                       float* __restrict__ fs, float* __restrict__ fv,
                       float* __restrict__ ns, float* __restrict__ nv)
{
    int t = blockIdx.x * blockDim.x + threadIdx.x;
    if (t >= NE * 64) return;
    int e = t >> 6, u = t & 63;
    const float* w = wall + (size_t)e * 192;
    float g   = w[128 + u];
    float we0 = w[2 * u], we1 = w[2 * u + 1];
    float s0 = ang[e * 4], s1 = ang[e * 4 + 1], s2 = ang[e * 4 + 2], s3 = ang[e * 4 + 3];
    fs[t] *= g;
    size_t fb = (size_t)e * 192 + u;
    fv[fb]       *= g;
    fv[fb + 64]  *= g;
    fv[fb + 128] *= g;
    int ce = center[e];
    atomicAdd(&ns[(size_t)ce * 64 + u], we0 * s0);
    size_t nb = (size_t)ce * 192 + u;
    atomicAdd(&nv[nb],       we1 * s1);
    atomicAdd(&nv[nb + 64],  we1 * s2);
    atomicAdd(&nv[nb + 128], we1 * s3);
}

__global__ void k_nodelin(const float* __restrict__ ns, const float* __restrict__ nv,
                          const float* __restrict__ w0, const float* __restrict__ w1,
                          float* __restrict__ ns2, float* __restrict__ nv2)
{
    __shared__ float sm[256];
    int n = blockIdx.x;
    int tid = threadIdx.x;
    if (tid < 64)       sm[tid] = ns[(size_t)n * 64 + tid] * INV_AVG;
    else                sm[tid] = nv[(size_t)n * 192 + (tid - 64)] * INV_AVG;
    __syncthreads();
    int v = tid & 63;
    int grp = tid >> 6;
    const float* w  = (grp == 0) ? w0 : w1;
    const float* in = (grp == 0) ? &sm[0] : &sm[grp * 64];
    float acc = 0.f;
    #pragma unroll 8
    for (int u = 0; u < 64; u++)
        acc = fmaf(in[u], w[u * 64 + v], acc);
    if (grp == 0) ns2[(size_t)n * 64 + v] = acc;
    else          nv2[(size_t)n * 192 + (grp - 1) * 64 + v] = acc;
}

__global__ void k_tp(const float* __restrict__ fs, const float* __restrict__ fv,
                     const float* __restrict__ ns2, const float* __restrict__ nv2,
                     const int* __restrict__ center,
                     float* __restrict__ ts, float* __restrict__ tv)
{
    int t = blockIdx.x * blockDim.x + threadIdx.x;
    if (t >= NE * 64) return;
    int e = t >> 6, u = t & 63;
    int ce = center[e];
    float s1  = fs[t];
    size_t fb = (size_t)e * 192 + u;
    float v1x = fv[fb], v1y = fv[fb + 64], v1z = fv[fb + 128];
    float s2  = ns2[(size_t)ce * 64 + u];
    size_t nb = (size_t)ce * 192 + u;
    float v2x = nv2[nb], v2y = nv2[nb + 64], v2z = nv2[nb + 128];

    ts[(size_t)e * 128 + u]      = s1 * s2;
    ts[(size_t)e * 128 + 64 + u] = (v1x * v2x + v1y * v2y + v1z * v2z) * INV_SQRT3;

    size_t tb = (size_t)e * 384;
    tv[tb + u]             = s1 * v2x * INV_SQRT3;
    tv[tb + 64 + u]        = v1x * s2 * INV_SQRT3;
    tv[tb + 128 + u]       = s1 * v2y * INV_SQRT3;
    tv[tb + 128 + 64 + u]  = v1y * s2 * INV_SQRT3;
    tv[tb + 256 + u]       = s1 * v2z * INV_SQRT3;
    tv[tb + 256 + 64 + u]  = v1z * s2 * INV_SQRT3;
}

__global__ void k_resid(float* __restrict__ lat, const float* __restrict__ nl,
                        const float* __restrict__ cut, const float* __restrict__ res_p)
{
    int t = blockIdx.x * blockDim.x + threadIdx.x;
    if (t >= NE * 256) return;
    float a = 1.f / (1.f + expf(-res_p[1]));
    float sa = sqrtf(1.f - a), sb = sqrtf(a);
    int e = t >> 8;
    lat[t] = sa * lat[t] + sb * cut[e] * nl[t];
}

__global__ void k_transpose(const float* __restrict__ sw, const float* __restrict__ vw,
                            float* __restrict__ WS, float* __restrict__ WV)
{
    int t = blockIdx.x * blockDim.x + threadIdx.x;
    if (t >= 2 * 2 * 64 * 64) return;
    int v = t & 63;
    int u = (t >> 6) & 63;
    int o = (t >> 12) & 1;
    int i = (t >> 13) & 1;
    int dst = (i * 64 + u) * 128 + (o * 64 + v);
    WS[dst] = sw[t];
    WV[dst] = vw[t];
}

__global__ void k_out(const float* __restrict__ fso, const float* __restrict__ fvo,
                      const float* __restrict__ fin, float* __restrict__ out)
{
    int t = blockIdx.x * blockDim.x + threadIdx.x;
    if (t >= NE * 512) return;
    int e = t >> 9;
    int j = t & 511;
    if (j < 128) {
        out[t] = fso[(size_t)e * 128 + j] * fin[(size_t)e * 128 + j];
    } else {
        int r = j - 128;
        int o = r / 192;
        int q = r - o * 192;
        int v = q / 3;
        int c = q - v * 3;
        out[t] = fvo[((size_t)e * 3 + c) * 128 + o * 64 + v];
    }
}

// ---------------------------------------------------------------------------
// Host orchestration
// ---------------------------------------------------------------------------
static inline int cdiv(int a, int b) { return (a + b - 1) / b; }

static void run_gemm(const float* A1, int K1, int lda1,
                     const float* A2, int lda2,
                     const float* W, float* C,
                     int M, int N, int K, int act, const float* rs)
{
    dim3 grid(N / 64, cdiv(M, 128));
    gemm_tc<<<grid, 256>>>(A1, K1, lda1, A2, lda2, W, C, M, N, K, act, rs);
}

extern "C" void kernel_launch(void* const* d_in, const int* in_sizes, int n_in,
                              void* d_out, int out_size)
{
    const float* node_attrs = (const float*)d_in[0];
    const float* radial     = (const float*)d_in[1];
    const float* ang        = (const float*)d_in[2];
    const float* lens       = (const float*)d_in[3];
    const int*   eidx       = (const int*)d_in[4];
    const float* tb_w0      = (const float*)d_in[5];
    const float* tb_w1      = (const float*)d_in[6];
    const float* tb_w2      = (const float*)d_in[7];
    const float* lat1_w0    = (const float*)d_in[8];
    const float* lat1_w1    = (const float*)d_in[9];
    const float* env0_w     = (const float*)d_in[10];
    const float* env1_w     = (const float*)d_in[11];
    const float* envlin0    = (const float*)d_in[12];
    const float* envlin1    = (const float*)d_in[13];
    const float* lin0_sw    = (const float*)d_in[14];
    const float* lin0_vw    = (const float*)d_in[15];
    const float* lin1_sw    = (const float*)d_in[16];
    const float* lin1_vw    = (const float*)d_in[17];
    const float* fin_w0     = (const float*)d_in[18];
    const float* fin_w1     = (const float*)d_in[19];
    const float* res_p      = (const float*)d_in[20];
    float* out = (float*)d_out;

    float* S = nullptr;
    cudaGetSymbolAddress((void**)&S, g_scratch);

    float* CUT  = S + OFF_CUT;
    float* X0   = S + OFF_X0;
    float* H0   = S + OFF_H0;
    float* H1   = S + OFF_H1;
    float* LAT  = S + OFF_LAT;
    float* WALL = S + OFF_WALL;
    float* FS   = S + OFF_FS;
    float* FV   = S + OFF_FV;
    float* FS2  = S + OFF_FS2;
    float* FV2  = S + OFF_FV2;
    float* TS   = S + OFF_TS;
    float* TV   = S + OFF_TV;
    float* FSO  = S + OFF_FSO;
    float* FVO  = S + OFF_FVO;
    float* FIN  = S + OFF_FIN2;
    float* NS   = S + OFF_NS;
    float* NV   = S + OFF_NV;
    float* NS2  = S + OFF_NS2;
    float* NV2  = S + OFF_NV2;
    float* WS   = S + OFF_WSC;
    float* WV   = S + OFF_WVC;

    const int T = 256;

    k_cut<<<cdiv(NE, T), T>>>(lens, CUT);
    k_gather<<<cdiv(NE * 136, T), T>>>(node_attrs, radial, eidx, X0);

    // two-body MLP -> latents (cut in epilogue of last layer)
    run_gemm(X0, 136, 136, nullptr, 0, tb_w0, H0, NE, 256, 136, 1, nullptr);
    run_gemm(H0, 256, 256, nullptr, 0, tb_w1, H1, NE, 256, 256, 1, nullptr);
    run_gemm(H1, 256, 256, nullptr, 0, tb_w2, LAT, NE, 256, 256, 0, CUT);

    // env0
    run_gemm(LAT, 256, 256, nullptr, 0, env0_w, WALL, NE, 320, 256, 0, nullptr);
    k_zero<<<cdiv(NN * 256, T), T>>>(NS, NN * 256);
    k_env0<<<cdiv(NE * 64, T), T>>>(WALL, ang, eidx, FS, FV, NS, NV);
    k_nodelin<<<NN, 256>>>(NS, NV, envlin0, envlin0 + 4096, NS2, NV2);

    // tensor product 1
    k_tp<<<cdiv(NE * 64, T), T>>>(FS, FV, NS2, NV2, eidx, TS, TV);

    // lin0
    run_gemm(TS, 128, 128, nullptr, 0, lin0_sw, FS2, NE, 64, 128, 0, nullptr);
    run_gemm(TV, 128, 128, nullptr, 0, lin0_vw, FV2, 3 * NE, 64, 128, 0, nullptr);

    // latent MLP + residual
    run_gemm(LAT, 256, 256, TS, 128, lat1_w0, H0, NE, 256, 384, 1, nullptr);
    run_gemm(H0, 256, 256, nullptr, 0, lat1_w1, H1, NE, 256, 256, 0, nullptr);
    k_resid<<<cdiv(NE * 256, T), T>>>(LAT, H1, CUT, res_p);

    // env1
    run_gemm(LAT, 256, 256, nullptr, 0, env1_w, WALL, NE, 192, 256, 0, nullptr);
    k_zero<<<cdiv(NN * 256, T), T>>>(NS, NN * 256);
    k_env1<<<cdiv(NE * 64, T), T>>>(WALL, ang, eidx, FS2, FV2, NS, NV);
    k_nodelin<<<NN, 256>>>(NS, NV, envlin1, envlin1 + 4096, NS2, NV2);

    // tensor product 2
    k_tp<<<cdiv(NE * 64, T), T>>>(FS2, FV2, NS2, NV2, eidx, TS, TV);

    // lin1
    k_transpose<<<cdiv(16384, T), T>>>(lin1_sw, lin1_vw, WS, WV);
    run_gemm(TS, 128, 128, nullptr, 0, WS, FSO, NE, 128, 128, 0, nullptr);
    run_gemm(TV, 128, 128, nullptr, 0, WV, FVO, 3 * NE, 128, 128, 0, nullptr);

    // final MLP
    run_gemm(LAT, 256, 256, TS, 128, fin_w0, H0, NE, 256, 384, 1, nullptr);
    run_gemm(H0, 256, 256, nullptr, 0, fin_w1, FIN, NE, 128, 256, 0, nullptr);

    k_out<<<cdiv(NE * 512, T), T>>>(FSO, FVO, FIN, out);
}